// round 16
// baseline (speedup 1.0000x reference)
#include <cuda_runtime.h>
#include <cuda_fp16.h>
#include <cstdint>

#define BATCH 8
#define SEQ 4096
#define DIM 512
#define M_TOT (BATCH * SEQ)     // 32768
#define KTOT 3584               // 512 + 512*6
#define NTOT 512
#define GN 10
#define NBASE 6

// GEMM tiling (proven config — frozen at 366 us)
#define BM 128
#define BN 128
#define BK 64
#define STAGES 3
#define NSTG (KTOT / BK)        // 56
#define ASTR 72
#define BSTR 72
#define A_HALFS (BM * ASTR)
#define B_HALFS (BN * BSTR)
#define SM_B_OFF (STAGES * A_HALFS)
#define SMEM_BYTES ((SM_B_OFF + STAGES * B_HALFS) * 2)   // 110592

// prep layout: 8 tokens per 256-thread block (1 warp per token)
#define PREP_TOK_BLOCKS (M_TOT / 8)      // 4096
#define PREP_W_BLOCKS   (NTOT / 8)       // 64

// ---------------- scratch ----------------------------------------------------
__device__ __half g_A[(size_t)M_TOT * KTOT];   // activations [M, K]
__device__ __half g_W[(size_t)NTOT * KTOT];    // weight^T [N, K]

// ---------------- helpers ---------------------------------------------------
__device__ __forceinline__ void cp_async16(void* smem, const void* gmem) {
    uint32_t s = (uint32_t)__cvta_generic_to_shared(smem);
    asm volatile("cp.async.cg.shared.global [%0], [%1], 16;" :: "r"(s), "l"(gmem));
}
#define CP_COMMIT() asm volatile("cp.async.commit_group;")
#define CP_WAIT1()  asm volatile("cp.async.wait_group 1;")

__device__ __forceinline__ void ldsm_x4(uint32_t* r, const __half* p) {
    uint32_t a = (uint32_t)__cvta_generic_to_shared(p);
    asm volatile("ldmatrix.sync.aligned.m8n8.x4.shared.b16 {%0,%1,%2,%3}, [%4];"
                 : "=r"(r[0]), "=r"(r[1]), "=r"(r[2]), "=r"(r[3]) : "r"(a));
}

__device__ __forceinline__ void mma_f16(float* d, const uint32_t* a, const uint32_t* b) {
    asm volatile(
        "mma.sync.aligned.m16n8k16.row.col.f32.f16.f16.f32 "
        "{%0,%1,%2,%3}, {%4,%5,%6,%7}, {%8,%9}, {%0,%1,%2,%3};"
        : "+f"(d[0]), "+f"(d[1]), "+f"(d[2]), "+f"(d[3])
        : "r"(a[0]), "r"(a[1]), "r"(a[2]), "r"(a[3]), "r"(b[0]), "r"(b[1]));
}

// ---------------- kernel 1: prep --------------------------------------------
// blocks [0, 4096): act — 1 warp per token, 16 feats/lane.
// blocks [4096, 4160): W-build — one W^T row per warp.
__global__ void __launch_bounds__(256) prep_kernel(const float* __restrict__ x,
                                                   const float* __restrict__ ln_w,
                                                   const float* __restrict__ ln_b,
                                                   const float* __restrict__ grid,
                                                   const float* __restrict__ base_w,
                                                   const float* __restrict__ spline_w) {
    int warp = threadIdx.x >> 5, lane = threadIdx.x & 31;

    if (blockIdx.x >= PREP_TOK_BLOCKS) {
        int n = (blockIdx.x - PREP_TOK_BLOCKS) * 8 + warp;
        __half* wrow = g_W + (size_t)n * KTOT;
        #pragma unroll
        for (int i = 0; i < KTOT / 32; i++) {
            int k = lane + i * 32;
            float v = (k < DIM) ? base_w[(size_t)k * NTOT + n]
                                : spline_w[(size_t)n * (KTOT - DIM) + (k - DIM)];
            wrow[k] = __float2half_rn(v);
        }
        return;
    }

    int token = blockIdx.x * 8 + warp;
    const float* xrow = x + (size_t)token * DIM;
    int d0 = lane * 16;

    // LN stats
    float s = 0.f, ss = 0.f;
    #pragma unroll
    for (int q = 0; q < 4; q++) {
        float4 v = reinterpret_cast<const float4*>(xrow + d0)[q];
        s  += v.x + v.y + v.z + v.w;
        ss += v.x * v.x + v.y * v.y + v.z * v.z + v.w * v.w;
    }
    #pragma unroll
    for (int o = 16; o > 0; o >>= 1) {
        s  += __shfl_xor_sync(0xffffffffu, s, o);
        ss += __shfl_xor_sync(0xffffffffu, ss, o);
    }
    float mean = s * (1.0f / DIM);
    float var  = ss * (1.0f / DIM) - mean * mean;
    float rstd = rsqrtf(var + 1e-5f);

    // uniform grid: need g0 and 1/h only
    float g0 = __ldg(grid + 0);
    float invh = __fdividef(1.0f, __ldg(grid + 1) - g0);

    __half* arow = g_A + (size_t)token * KTOT;

    #pragma unroll
    for (int grp = 0; grp < 2; grp++) {
        int db = d0 + grp * 8;
        float4 v0 = reinterpret_cast<const float4*>(xrow + db)[0];
        float4 v1 = reinterpret_cast<const float4*>(xrow + db)[1];
        float xs[8] = {v0.x, v0.y, v0.z, v0.w, v1.x, v1.y, v1.z, v1.w};
        float4 w0 = reinterpret_cast<const float4*>(ln_w + db)[0];
        float4 w1 = reinterpret_cast<const float4*>(ln_w + db)[1];
        float4 c0 = reinterpret_cast<const float4*>(ln_b + db)[0];
        float4 c1 = reinterpret_cast<const float4*>(ln_b + db)[1];
        float lw[8] = {w0.x, w0.y, w0.z, w0.w, w1.x, w1.y, w1.z, w1.w};
        float lb[8] = {c0.x, c0.y, c0.z, c0.w, c1.x, c1.y, c1.z, c1.w};

        __half sil[8];
        __half bas[48];

        #pragma unroll
        for (int j = 0; j < 8; j++) {
            float xn = (xs[j] - mean) * rstd * lw[j] + lb[j];
            float sl = xn / (1.0f + __expf(-xn));
            sil[j] = __float2half_rn(sl);

            // closed-form uniform cubic B-spline: cell c, local u in [0,1)
            float t  = (xn - g0) * invh;
            float cf = floorf(t);
            float u  = t - cf;
            int c = (int)cf;
            if (c < 0 || c > 8) c = -100;      // out of knot span -> all bases 0

            float u2 = u * u, u3 = u2 * u;
            float um = 1.0f - u;
            float P0 = u3 * (1.0f / 6.0f);                              // basis index c
            float P1 = ((-0.5f * u + 0.5f) * u + 0.5f) * u + (1.0f/6.0f); // c-1
            float P2 = ((0.5f * u - 1.0f) * u) * u + (2.0f / 3.0f);       // c-2
            float P3 = um * um * um * (1.0f / 6.0f);                      // c-3

            #pragma unroll
            for (int i = 0; i < NBASE; i++) {
                int d = c - i;
                float v = (d == 0) ? P0 : (d == 1) ? P1 : (d == 2) ? P2
                         : (d == 3) ? P3 : 0.0f;
                bas[j * NBASE + i] = __float2half_rn(v);
            }
        }

        *reinterpret_cast<uint4*>(arow + db) = *reinterpret_cast<uint4*>(sil);
        uint4* bsrc = reinterpret_cast<uint4*>(bas);
        uint4* bdst = reinterpret_cast<uint4*>(arow + DIM + (size_t)db * NBASE);
        #pragma unroll
        for (int i = 0; i < 6; i++) bdst[i] = bsrc[i];
    }
}

// ---------------- kernel 2: fp16 GEMM 128x128, BK=64, 3-stage, 2 CTA/SM -----
__device__ __forceinline__ void load_stage(__half* sm, int stg, const __half* gA,
                                           int n0, int kt, int tid) {
    __half* As = sm + stg * A_HALFS;
    __half* Bs = sm + SM_B_OFF + stg * B_HALFS;
    #pragma unroll
    for (int i = 0; i < 4; i++) {
        int id = tid + i * 256;
        int r = id >> 3, c = id & 7;
        cp_async16(As + r * ASTR + c * 8, gA + (size_t)r * KTOT + kt + c * 8);
    }
    #pragma unroll
    for (int i = 0; i < 4; i++) {
        int id = tid + i * 256;
        int r = id >> 3, c = id & 7;
        cp_async16(Bs + r * BSTR + c * 8, g_W + (size_t)(n0 + r) * KTOT + kt + c * 8);
    }
    CP_COMMIT();
}

__global__ void __launch_bounds__(256, 2) gemm_kernel(float* __restrict__ out,
                                                      const float* __restrict__ bias) {
    extern __shared__ __half sm[];
    int tid = threadIdx.x;
    int lane = tid & 31, warp = tid >> 5;
    int wm = warp >> 2;
    int wn = warp & 3;
    int lr = lane >> 2, lc = lane & 3;

    int n0 = blockIdx.x * BN;
    int m0 = blockIdx.y * BM;
    const __half* gA = g_A + (size_t)m0 * KTOT;

    int a_row = (lane & 15);
    int a_koff = (lane >> 4) << 3;
    int b_row = (lane & 7) + ((lane & 16) >> 1);
    int b_koff = lane & 8;

    float acc[4][4][4];
    #pragma unroll
    for (int i = 0; i < 4; i++)
        #pragma unroll
        for (int j = 0; j < 4; j++)
            #pragma unroll
            for (int r = 0; r < 4; r++) acc[i][j][r] = 0.0f;

    load_stage(sm, 0, gA, n0, 0, tid);
    load_stage(sm, 1, gA, n0, BK, tid);

    for (int t = 0; t < NSTG; t++) {
        CP_WAIT1();
        __syncthreads();

        if (t + STAGES - 1 < NSTG)
            load_stage(sm, (t + STAGES - 1) % STAGES, gA, n0, (t + STAGES - 1) * BK, tid);
        else
            CP_COMMIT();

        int stg = t % STAGES;
        const __half* As = sm + stg * A_HALFS;
        const __half* Bs = sm + SM_B_OFF + stg * B_HALFS;

        #pragma unroll
        for (int kk = 0; kk < 4; kk++) {
            int k0 = kk * 16;
            uint32_t af[4][4];
            #pragma unroll
            for (int mt = 0; mt < 4; mt++) {
                int row = wm * 64 + mt * 16 + a_row;
                ldsm_x4(af[mt], As + row * ASTR + k0 + a_koff);
            }
            uint32_t bf[4][2];
            #pragma unroll
            for (int np = 0; np < 2; np++) {
                uint32_t r[4];
                int col = wn * 32 + np * 16 + b_row;
                ldsm_x4(r, Bs + col * BSTR + k0 + b_koff);
                bf[np * 2][0] = r[0]; bf[np * 2][1] = r[1];
                bf[np * 2 + 1][0] = r[2]; bf[np * 2 + 1][1] = r[3];
            }
            #pragma unroll
            for (int mt = 0; mt < 4; mt++)
                #pragma unroll
                for (int nt = 0; nt < 4; nt++)
                    mma_f16(acc[mt][nt], af[mt], bf[nt]);
        }
    }

    #pragma unroll
    for (int mt = 0; mt < 4; mt++) {
        #pragma unroll
        for (int nt = 0; nt < 4; nt++) {
            int row = m0 + wm * 64 + mt * 16 + lr;
            int col = n0 + wn * 32 + nt * 8 + lc * 2;
            float b0 = __ldg(bias + col), b1 = __ldg(bias + col + 1);
            float2 v0 = make_float2(acc[mt][nt][0] + b0, acc[mt][nt][1] + b1);
            float2 v1 = make_float2(acc[mt][nt][2] + b0, acc[mt][nt][3] + b1);
            *reinterpret_cast<float2*>(out + (size_t)row * NTOT + col) = v0;
            *reinterpret_cast<float2*>(out + (size_t)(row + 8) * NTOT + col) = v1;
        }
    }
}

// ---------------- launch -----------------------------------------------------
extern "C" void kernel_launch(void* const* d_in, const int* in_sizes, int n_in,
                              void* d_out, int out_size) {
    const float* x        = (const float*)d_in[0];
    const float* ln_w     = (const float*)d_in[1];
    const float* ln_b     = (const float*)d_in[2];
    const float* base_w   = (const float*)d_in[3];
    const float* base_b   = (const float*)d_in[4];
    const float* spline_w = (const float*)d_in[5];
    const float* grid     = (const float*)d_in[6];
    float* out = (float*)d_out;

    cudaFuncSetAttribute(gemm_kernel, cudaFuncAttributeMaxDynamicSharedMemorySize, SMEM_BYTES);

    prep_kernel<<<PREP_TOK_BLOCKS + PREP_W_BLOCKS, 256>>>(x, ln_w, ln_b, grid,
                                                          base_w, spline_w);
    dim3 g(NTOT / BN, M_TOT / BM);    // (4, 256)
    gemm_kernel<<<g, 256, SMEM_BYTES>>>(out, base_b);
}

// round 17
// speedup vs baseline: 1.3142x; 1.3142x over previous
#include <cuda_runtime.h>
#include <cuda_fp16.h>
#include <cstdint>

#define BATCH 8
#define SEQ 4096
#define DIM 512
#define M_TOT (BATCH * SEQ)     // 32768
#define KTOT 3584               // 512 + 512*6
#define NTOT 512
#define GN 10
#define NBASE 6

// GEMM tiling (proven config — frozen at ~364 us)
#define BM 128
#define BN 128
#define BK 64
#define STAGES 3
#define NSTG (KTOT / BK)        // 56
#define ASTR 72
#define BSTR 72
#define A_HALFS (BM * ASTR)
#define B_HALFS (BN * BSTR)
#define SM_B_OFF (STAGES * A_HALFS)
#define SMEM_BYTES ((SM_B_OFF + STAGES * B_HALFS) * 2)   // 110592

// prep layout: 8 tokens per 256-thread block (1 warp per token)
#define PREP_TOK_BLOCKS (M_TOT / 8)      // 4096
#define PREP_W_BLOCKS   (NTOT / 8)       // 64

// ---------------- scratch ----------------------------------------------------
__device__ __half g_A[(size_t)M_TOT * KTOT];   // activations [M, K]
__device__ __half g_W[(size_t)NTOT * KTOT];    // weight^T [N, K]

// ---------------- helpers ---------------------------------------------------
__device__ __forceinline__ void cp_async16(void* smem, const void* gmem) {
    uint32_t s = (uint32_t)__cvta_generic_to_shared(smem);
    asm volatile("cp.async.cg.shared.global [%0], [%1], 16;" :: "r"(s), "l"(gmem));
}
#define CP_COMMIT() asm volatile("cp.async.commit_group;")
#define CP_WAIT1()  asm volatile("cp.async.wait_group 1;")

__device__ __forceinline__ void ldsm_x4(uint32_t* r, const __half* p) {
    uint32_t a = (uint32_t)__cvta_generic_to_shared(p);
    asm volatile("ldmatrix.sync.aligned.m8n8.x4.shared.b16 {%0,%1,%2,%3}, [%4];"
                 : "=r"(r[0]), "=r"(r[1]), "=r"(r[2]), "=r"(r[3]) : "r"(a));
}

__device__ __forceinline__ void mma_f16(float* d, const uint32_t* a, const uint32_t* b) {
    asm volatile(
        "mma.sync.aligned.m16n8k16.row.col.f32.f16.f16.f32 "
        "{%0,%1,%2,%3}, {%4,%5,%6,%7}, {%8,%9}, {%0,%1,%2,%3};"
        : "+f"(d[0]), "+f"(d[1]), "+f"(d[2]), "+f"(d[3])
        : "r"(a[0]), "r"(a[1]), "r"(a[2]), "r"(a[3]), "r"(b[0]), "r"(b[1]));
}

// ---------------- kernel 1: prep (R15-proven: ~88 us) ------------------------
// blocks [0, 4096): act — 1 warp per token, 16 feats/lane.
// blocks [4096, 4160): W-build — one W^T row per warp.
__global__ void __launch_bounds__(256) prep_kernel(const float* __restrict__ x,
                                                   const float* __restrict__ ln_w,
                                                   const float* __restrict__ ln_b,
                                                   const float* __restrict__ grid,
                                                   const float* __restrict__ base_w,
                                                   const float* __restrict__ spline_w) {
    int warp = threadIdx.x >> 5, lane = threadIdx.x & 31;

    if (blockIdx.x >= PREP_TOK_BLOCKS) {
        // ---- build W^T [N, K] in fp16, one row per warp ----
        int n = (blockIdx.x - PREP_TOK_BLOCKS) * 8 + warp;
        __half* wrow = g_W + (size_t)n * KTOT;
        #pragma unroll
        for (int i = 0; i < KTOT / 32; i++) {
            int k = lane + i * 32;
            float v = (k < DIM) ? base_w[(size_t)k * NTOT + n]
                                : spline_w[(size_t)n * (KTOT - DIM) + (k - DIM)];
            wrow[k] = __float2half_rn(v);
        }
        return;
    }

    // ---- act: one warp per token ----
    int token = blockIdx.x * 8 + warp;
    const float* xrow = x + (size_t)token * DIM;
    int d0 = lane * 16;

    float s = 0.f, ss = 0.f;
    #pragma unroll
    for (int q = 0; q < 4; q++) {
        float4 v = reinterpret_cast<const float4*>(xrow + d0)[q];
        s  += v.x + v.y + v.z + v.w;
        ss += v.x * v.x + v.y * v.y + v.z * v.z + v.w * v.w;
    }
    #pragma unroll
    for (int o = 16; o > 0; o >>= 1) {
        s  += __shfl_xor_sync(0xffffffffu, s, o);
        ss += __shfl_xor_sync(0xffffffffu, ss, o);
    }
    float mean = s * (1.0f / DIM);
    float var  = ss * (1.0f / DIM) - mean * mean;
    float rstd = rsqrtf(var + 1e-5f);

    // knots + fast reciprocal denominators (MUFU.RCP, ~1 ulp)
    float gg[GN];
    #pragma unroll
    for (int i = 0; i < GN; i++) gg[i] = __ldg(grid + i);
    float r1[GN - 1], r2[GN - 2], r3[GN - 3];
    #pragma unroll
    for (int i = 0; i < GN - 1; i++) r1[i] = __fdividef(1.0f, gg[i + 1] - gg[i]);
    #pragma unroll
    for (int i = 0; i < GN - 2; i++) r2[i] = __fdividef(1.0f, gg[i + 2] - gg[i]);
    #pragma unroll
    for (int i = 0; i < GN - 3; i++) r3[i] = __fdividef(1.0f, gg[i + 3] - gg[i]);

    __half* arow = g_A + (size_t)token * KTOT;

    #pragma unroll
    for (int grp = 0; grp < 2; grp++) {
        int db = d0 + grp * 8;
        float4 v0 = reinterpret_cast<const float4*>(xrow + db)[0];
        float4 v1 = reinterpret_cast<const float4*>(xrow + db)[1];
        float xs[8] = {v0.x, v0.y, v0.z, v0.w, v1.x, v1.y, v1.z, v1.w};
        float4 w0 = reinterpret_cast<const float4*>(ln_w + db)[0];
        float4 w1 = reinterpret_cast<const float4*>(ln_w + db)[1];
        float4 c0 = reinterpret_cast<const float4*>(ln_b + db)[0];
        float4 c1 = reinterpret_cast<const float4*>(ln_b + db)[1];
        float lw[8] = {w0.x, w0.y, w0.z, w0.w, w1.x, w1.y, w1.z, w1.w};
        float lb[8] = {c0.x, c0.y, c0.z, c0.w, c1.x, c1.y, c1.z, c1.w};

        __half sil[8];
        __half bas[48];

        #pragma unroll
        for (int j = 0; j < 8; j++) {
            float xn = (xs[j] - mean) * rstd * lw[j] + lb[j];
            float sl = xn / (1.0f + __expf(-xn));
            sil[j] = __float2half_rn(sl);

            float b[GN - 1];
            #pragma unroll
            for (int i = 0; i < GN - 1; i++)
                b[i] = (xn >= gg[i] && xn < gg[i + 1]) ? 1.0f : 0.0f;
            #pragma unroll
            for (int i = 0; i < GN - 2; i++) {
                float left  = (xn - gg[i]) * r1[i];
                float right = (gg[i + 2] - xn) * r1[i + 1];
                b[i] = left * b[i] + right * b[i + 1];
            }
            #pragma unroll
            for (int i = 0; i < GN - 3; i++) {
                float left  = (xn - gg[i]) * r2[i];
                float right = (gg[i + 3] - xn) * r2[i + 1];
                b[i] = left * b[i] + right * b[i + 1];
            }
            #pragma unroll
            for (int i = 0; i < GN - 4; i++) {
                float left  = (xn - gg[i]) * r3[i];
                float right = (gg[i + 4] - xn) * r3[i + 1];
                b[i] = left * b[i] + right * b[i + 1];
            }
            #pragma unroll
            for (int i = 0; i < NBASE; i++)
                bas[j * NBASE + i] = __float2half_rn(b[i]);
        }

        *reinterpret_cast<uint4*>(arow + db) = *reinterpret_cast<uint4*>(sil);
        uint4* bsrc = reinterpret_cast<uint4*>(bas);
        uint4* bdst = reinterpret_cast<uint4*>(arow + DIM + (size_t)db * NBASE);
        #pragma unroll
        for (int i = 0; i < 6; i++) bdst[i] = bsrc[i];
    }
}

// ---------------- kernel 2: fp16 GEMM 128x128, BK=64, 3-stage, 2 CTA/SM -----
// (R13/R16-proven: ~364 us, no stagger)
__device__ __forceinline__ void load_stage(__half* sm, int stg, const __half* gA,
                                           int n0, int kt, int tid) {
    __half* As = sm + stg * A_HALFS;
    __half* Bs = sm + SM_B_OFF + stg * B_HALFS;
    #pragma unroll
    for (int i = 0; i < 4; i++) {
        int id = tid + i * 256;
        int r = id >> 3, c = id & 7;
        cp_async16(As + r * ASTR + c * 8, gA + (size_t)r * KTOT + kt + c * 8);
    }
    #pragma unroll
    for (int i = 0; i < 4; i++) {
        int id = tid + i * 256;
        int r = id >> 3, c = id & 7;
        cp_async16(Bs + r * BSTR + c * 8, g_W + (size_t)(n0 + r) * KTOT + kt + c * 8);
    }
    CP_COMMIT();
}

__global__ void __launch_bounds__(256, 2) gemm_kernel(float* __restrict__ out,
                                                      const float* __restrict__ bias) {
    extern __shared__ __half sm[];
    int tid = threadIdx.x;
    int lane = tid & 31, warp = tid >> 5;
    int wm = warp >> 2;
    int wn = warp & 3;
    int lr = lane >> 2, lc = lane & 3;

    int n0 = blockIdx.x * BN;
    int m0 = blockIdx.y * BM;
    const __half* gA = g_A + (size_t)m0 * KTOT;

    int a_row = (lane & 15);
    int a_koff = (lane >> 4) << 3;
    int b_row = (lane & 7) + ((lane & 16) >> 1);
    int b_koff = lane & 8;

    float acc[4][4][4];
    #pragma unroll
    for (int i = 0; i < 4; i++)
        #pragma unroll
        for (int j = 0; j < 4; j++)
            #pragma unroll
            for (int r = 0; r < 4; r++) acc[i][j][r] = 0.0f;

    load_stage(sm, 0, gA, n0, 0, tid);
    load_stage(sm, 1, gA, n0, BK, tid);

    for (int t = 0; t < NSTG; t++) {
        CP_WAIT1();
        __syncthreads();

        if (t + STAGES - 1 < NSTG)
            load_stage(sm, (t + STAGES - 1) % STAGES, gA, n0, (t + STAGES - 1) * BK, tid);
        else
            CP_COMMIT();

        int stg = t % STAGES;
        const __half* As = sm + stg * A_HALFS;
        const __half* Bs = sm + SM_B_OFF + stg * B_HALFS;

        #pragma unroll
        for (int kk = 0; kk < 4; kk++) {
            int k0 = kk * 16;
            uint32_t af[4][4];
            #pragma unroll
            for (int mt = 0; mt < 4; mt++) {
                int row = wm * 64 + mt * 16 + a_row;
                ldsm_x4(af[mt], As + row * ASTR + k0 + a_koff);
            }
            uint32_t bf[4][2];
            #pragma unroll
            for (int np = 0; np < 2; np++) {
                uint32_t r[4];
                int col = wn * 32 + np * 16 + b_row;
                ldsm_x4(r, Bs + col * BSTR + k0 + b_koff);
                bf[np * 2][0] = r[0]; bf[np * 2][1] = r[1];
                bf[np * 2 + 1][0] = r[2]; bf[np * 2 + 1][1] = r[3];
            }
            #pragma unroll
            for (int mt = 0; mt < 4; mt++)
                #pragma unroll
                for (int nt = 0; nt < 4; nt++)
                    mma_f16(acc[mt][nt], af[mt], bf[nt]);
        }
    }

    #pragma unroll
    for (int mt = 0; mt < 4; mt++) {
        #pragma unroll
        for (int nt = 0; nt < 4; nt++) {
            int row = m0 + wm * 64 + mt * 16 + lr;
            int col = n0 + wn * 32 + nt * 8 + lc * 2;
            float b0 = __ldg(bias + col), b1 = __ldg(bias + col + 1);
            float2 v0 = make_float2(acc[mt][nt][0] + b0, acc[mt][nt][1] + b1);
            float2 v1 = make_float2(acc[mt][nt][2] + b0, acc[mt][nt][3] + b1);
            *reinterpret_cast<float2*>(out + (size_t)row * NTOT + col) = v0;
            *reinterpret_cast<float2*>(out + (size_t)(row + 8) * NTOT + col) = v1;
        }
    }
}

// ---------------- launch -----------------------------------------------------
extern "C" void kernel_launch(void* const* d_in, const int* in_sizes, int n_in,
                              void* d_out, int out_size) {
    const float* x        = (const float*)d_in[0];
    const float* ln_w     = (const float*)d_in[1];
    const float* ln_b     = (const float*)d_in[2];
    const float* base_w   = (const float*)d_in[3];
    const float* base_b   = (const float*)d_in[4];
    const float* spline_w = (const float*)d_in[5];
    const float* grid     = (const float*)d_in[6];
    float* out = (float*)d_out;

    cudaFuncSetAttribute(gemm_kernel, cudaFuncAttributeMaxDynamicSharedMemorySize, SMEM_BYTES);

    prep_kernel<<<PREP_TOK_BLOCKS + PREP_W_BLOCKS, 256>>>(x, ln_w, ln_b, grid,
                                                          base_w, spline_w);
    dim3 g(NTOT / BN, M_TOT / BM);    // (4, 256)
    gemm_kernel<<<g, 256, SMEM_BYTES>>>(out, base_b);
}